// round 14
// baseline (speedup 1.0000x reference)
#include <cuda_runtime.h>
#include <cstdint>
#include <math.h>

// Problem constants
#define B_   4
#define NH   8
#define HD   32
#define NS   2304     // 48*48
#define CC   256
#define TQ   128      // q rows per CTA (4 warps x 32)
#define TK   64       // kv rows per tile
#define NT   (NS / TK) // 36

// dynamic smem layout (float offsets), K/V double-buffered; norms pre-folded
#define PW_OFF  0                          // per-warp P: 4 x [32][68] (Q staging overlaps)
#define QP_OFF  0                          // Q staging [32][136]
#define KT_OFF(bf)  (8704  + (bf) * 2304)  // K^ [64][36] k-interleaved (normalized)
#define VP_OFF(bf)  (13312 + (bf) * 2176)  // V~ [32][68] (c rows, rho(j) cols)
#define SM_FLOATS 17664
#define SM_BYTES  (SM_FLOATS * 4)          // 70656 B -> 3 CTAs/SM = 207KB

__device__ float g_pre[B_ * CC * NS];

__device__ __forceinline__ float tf32r(float x) {
    uint32_t u;
    asm("cvt.rna.tf32.f32 %0, %1;" : "=r"(u) : "f"(x));
    return __uint_as_float(u);
}
__device__ __forceinline__ uint32_t fb(float x) { return __float_as_uint(x); }
__device__ __forceinline__ float ex2f(float x) {
    float y;
    asm("ex2.approx.f32 %0, %1;" : "=f"(y) : "f"(x));
    return y;
}

__device__ __forceinline__ void mma_tf32(float& c0, float& c1, float& c2, float& c3,
                                         uint32_t a0, uint32_t a1, uint32_t a2, uint32_t a3,
                                         uint32_t b0, uint32_t b1) {
    asm volatile("mma.sync.aligned.m16n8k8.row.col.f32.tf32.tf32.f32 "
                 "{%0,%1,%2,%3}, {%4,%5,%6,%7}, {%8,%9}, {%0,%1,%2,%3};"
                 : "+f"(c0), "+f"(c1), "+f"(c2), "+f"(c3)
                 : "r"(a0), "r"(a1), "r"(a2), "r"(a3), "r"(b0), "r"(b1));
}

// ---------------------------------------------------------------------------
// Fused attention, tf32 mma.sync, double-buffered K/V, occ 3 (reg-thinned).
// Normalizations folded into operands: Q^ = q*temp*log2e/||q||, K^ = k/||k||.
// Softmax is just p = 2^max(S,0). No reg-prefetch (liveness kept short).
// ---------------------------------------------------------------------------
__global__ __launch_bounds__(128, 3) void attn_kernel(
    const float* __restrict__ qkv, const float* __restrict__ temp)
{
    extern __shared__ float sm[];

    const int tid  = threadIdx.x;
    const int lane = tid & 31;
    const int w    = tid >> 5;       // warp 0..3 -> q rows w*32..
    const int q4   = lane & 3;
    const int g    = lane >> 2;

    const int bh = blockIdx.y;
    const int b  = bh >> 3, hh = bh & 7;
    const int n0 = blockIdx.x * TQ;
    const float th = temp[hh] * 1.44269504089f;   // temp * log2e

    const size_t baseQ = ((size_t)(b * 3 * CC) + hh * HD) * NS;
    const size_t baseK = baseQ + (size_t)CC * NS;
    const size_t baseV = baseK + (size_t)CC * NS;

    // role split: threads 0-63 own K row j=tid; threads 64-127 own V row j=tid-64
    const int jK = tid;
    const int jV = tid - 64;
    const int rjV = (jV & 3) * 16 + (jV >> 2);
    const bool isK = tid < 64;

    // ---- Q tile: thread owns q row n=tid; fold temp*log2e/||q|| into values ----
    {
        float qb[HD];
        float sq = 0.f;
        #pragma unroll
        for (int c = 0; c < HD; c++) {
            float v = qkv[baseQ + (size_t)c * NS + n0 + tid];
            sq += v * v;
            qb[c] = v;
        }
        const float qscale = th / fmaxf(sqrtf(sq), 1e-12f);
        #pragma unroll
        for (int c = 0; c < HD; c++)
            sm[QP_OFF + c * 136 + tid] = tf32r(qb[c] * qscale);
    }
    __syncthreads();

    // ---- persistent Q A-frags ----
    uint32_t aq[4][2][4];
    #pragma unroll
    for (int kc = 0; kc < 4; kc++)
        #pragma unroll
        for (int mt = 0; mt < 2; mt++) {
            int R = w * 32 + mt * 16 + g;
            aq[kc][mt][0] = fb(sm[QP_OFF + (8 * kc + q4) * 136 + R]);
            aq[kc][mt][1] = fb(sm[QP_OFF + (8 * kc + q4) * 136 + R + 8]);
            aq[kc][mt][2] = fb(sm[QP_OFF + (8 * kc + q4 + 4) * 136 + R]);
            aq[kc][mt][3] = fb(sm[QP_OFF + (8 * kc + q4 + 4) * 136 + R + 8]);
        }
    __syncthreads();   // QP staging dead -> PW region reusable

    // ---- direct gmem->convert->smem tile load; kbuf liveness is local ----
    #define LOAD_TILE(T, BF)                                                      \
    do {                                                                          \
        if (isK) {                                                                \
            float kbuf[HD];                                                       \
            float sk = 0.f;                                                       \
            _Pragma("unroll")                                                     \
            for (int c = 0; c < HD; c++) {                                        \
                float v = qkv[baseK + (size_t)c * NS + (T) * TK + jK];            \
                sk += v * v;                                                      \
                kbuf[c] = v;                                                      \
            }                                                                     \
            const float kscale = 1.0f / fmaxf(sqrtf(sk), 1e-12f);                 \
            _Pragma("unroll")                                                     \
            for (int c = 0; c < HD; c++) { kbuf[c] = tf32r(kbuf[c] * kscale); }   \
            _Pragma("unroll")                                                     \
            for (int q = 0; q < 4; q++)                                           \
                _Pragma("unroll")                                                 \
                for (int u = 0; u < 2; u++) {                                     \
                    float4 f = make_float4(kbuf[(4*u+0)*4+q], kbuf[(4*u+1)*4+q],  \
                                           kbuf[(4*u+2)*4+q], kbuf[(4*u+3)*4+q]); \
                    *(float4*)&sm[KT_OFF(BF) + jK * 36 + 8 * q + 4 * u] = f;      \
                }                                                                 \
        } else {                                                                  \
            _Pragma("unroll")                                                     \
            for (int c = 0; c < HD; c++)                                          \
                sm[VP_OFF(BF) + c * 68 + rjV] =                                   \
                    tf32r(qkv[baseV + (size_t)c * NS + (T) * TK + jV]);           \
        }                                                                         \
    } while (0)

    LOAD_TILE(0, 0);
    __syncthreads();

    float o[2][4][4] = {};
    float racc[2][2] = {};
    const int pwbase = PW_OFF + w * 2176;

    #pragma unroll 1
    for (int t = 0; t < NT; t++) {
        const int cur = t & 1, nxt = cur ^ 1;

        // ---- MMA1: S(32x64) = Q^(32x32) K^^T  (softmax arg directly) ----
        float s[2][8][4] = {};
        #pragma unroll
        for (int nt = 0; nt < 8; nt++) {
            const float4 bq0 = *(const float4*)&sm[KT_OFF(cur) + (nt * 8 + g) * 36 + 8 * q4];
            const float4 bq1 = *(const float4*)&sm[KT_OFF(cur) + (nt * 8 + g) * 36 + 8 * q4 + 4];
            #pragma unroll
            for (int mt = 0; mt < 2; mt++) {
                mma_tf32(s[mt][nt][0], s[mt][nt][1], s[mt][nt][2], s[mt][nt][3],
                         aq[0][mt][0], aq[0][mt][1], aq[0][mt][2], aq[0][mt][3], fb(bq0.x), fb(bq0.y));
                mma_tf32(s[mt][nt][0], s[mt][nt][1], s[mt][nt][2], s[mt][nt][3],
                         aq[1][mt][0], aq[1][mt][1], aq[1][mt][2], aq[1][mt][3], fb(bq0.z), fb(bq0.w));
                mma_tf32(s[mt][nt][0], s[mt][nt][1], s[mt][nt][2], s[mt][nt][3],
                         aq[2][mt][0], aq[2][mt][1], aq[2][mt][2], aq[2][mt][3], fb(bq1.x), fb(bq1.y));
                mma_tf32(s[mt][nt][0], s[mt][nt][1], s[mt][nt][2], s[mt][nt][3],
                         aq[3][mt][0], aq[3][mt][1], aq[3][mt][2], aq[3][mt][3], fb(bq1.z), fb(bq1.w));
            }
        }

        // ---- P = 2^max(S,0); raw f32 store (tf32 MMA truncates in HW) ----
        #pragma unroll
        for (int nt = 0; nt < 8; nt++) {
            const int rho = 32 * (q4 & 1) + 2 * nt + (q4 >> 1);
            #pragma unroll
            for (int mt = 0; mt < 2; mt++) {
                float p00 = ex2f(fmaxf(s[mt][nt][0], 0.f));
                float p01 = ex2f(fmaxf(s[mt][nt][1], 0.f));
                float p10 = ex2f(fmaxf(s[mt][nt][2], 0.f));
                float p11 = ex2f(fmaxf(s[mt][nt][3], 0.f));
                racc[mt][0] += p00 + p01;
                racc[mt][1] += p10 + p11;
                const int r0 = pwbase + (mt * 16 + g) * 68;
                const int r1 = r0 + 8 * 68;
                sm[r0 + rho]      = p00;
                sm[r0 + rho + 16] = p01;
                sm[r1 + rho]      = p10;
                sm[r1 + rho + 16] = p11;
            }
        }
        __syncwarp();

        // ---- reload P as A-frags ----
        float pa[2][16], pb[2][16];
        #pragma unroll
        for (int mt = 0; mt < 2; mt++) {
            const int r0 = pwbase + (mt * 16 + g) * 68 + 16 * q4;
            const int r1 = r0 + 8 * 68;
            #pragma unroll
            for (int u = 0; u < 4; u++) {
                *(float4*)&pa[mt][4 * u] = *(const float4*)&sm[r0 + 4 * u];
                *(float4*)&pb[mt][4 * u] = *(const float4*)&sm[r1 + 4 * u];
            }
        }

        // ---- MMA2: O(32x32) += P(32x64) V(64x32) ----
        #pragma unroll
        for (int nt2 = 0; nt2 < 4; nt2++) {
            float bv[16];
            const int vr = VP_OFF(cur) + (nt2 * 8 + g) * 68 + 16 * q4;
            #pragma unroll
            for (int u = 0; u < 4; u++)
                *(float4*)&bv[4 * u] = *(const float4*)&sm[vr + 4 * u];
            #pragma unroll
            for (int mt = 0; mt < 2; mt++)
                #pragma unroll
                for (int kc = 0; kc < 8; kc++)
                    mma_tf32(o[mt][nt2][0], o[mt][nt2][1], o[mt][nt2][2], o[mt][nt2][3],
                             fb(pa[mt][2 * kc]), fb(pb[mt][2 * kc]),
                             fb(pa[mt][2 * kc + 1]), fb(pb[mt][2 * kc + 1]),
                             fb(bv[2 * kc]), fb(bv[2 * kc + 1]));
        }

        // ---- load tile t+1 into buffer nxt (covered by peer CTAs at occ 3) ----
        if (t + 1 < NT) LOAD_TILE(t + 1, nxt);
        __syncthreads();
    }
    #undef LOAD_TILE

    // ---- rowsum reduce across the 4-lane q4 group ----
    #pragma unroll
    for (int mt = 0; mt < 2; mt++)
        #pragma unroll
        for (int hf = 0; hf < 2; hf++) {
            float v = racc[mt][hf];
            v += __shfl_xor_sync(0xffffffffu, v, 1);
            v += __shfl_xor_sync(0xffffffffu, v, 2);
            racc[mt][hf] = 1.0f / v;
        }

    // ---- write O to g_pre[b, hh*HD + c, n] ----
    const size_t baseO = ((size_t)(b * CC) + hh * HD) * NS;
    #pragma unroll
    for (int mt = 0; mt < 2; mt++) {
        const int row = n0 + w * 32 + mt * 16 + g;
        #pragma unroll
        for (int nt2 = 0; nt2 < 4; nt2++) {
            int c0 = nt2 * 8 + 2 * q4;
            g_pre[baseO + (size_t)c0 * NS + row]           = o[mt][nt2][0] * racc[mt][0];
            g_pre[baseO + (size_t)(c0 + 1) * NS + row]     = o[mt][nt2][1] * racc[mt][0];
            g_pre[baseO + (size_t)c0 * NS + row + 8]       = o[mt][nt2][2] * racc[mt][1];
            g_pre[baseO + (size_t)(c0 + 1) * NS + row + 8] = o[mt][nt2][3] * racc[mt][1];
        }
    }
}

// ---------------------------------------------------------------------------
// 1x1 conv as tf32 warp-MMA GEMM (round-8 version: 24.9us measured)
// ---------------------------------------------------------------------------
__global__ __launch_bounds__(256, 2) void proj_kernel(
    const float* __restrict__ W, const float* __restrict__ bias,
    float* __restrict__ out)
{
    __shared__ float Ws[32 * 136];   // [k][o], pitch 136
    __shared__ float Xs[64 * 36];    // [n][k-interleaved], pitch 36

    const int tid  = threadIdx.x;
    const int lane = tid & 31;
    const int w    = tid >> 5;
    const int q4   = lane & 3;
    const int g    = lane >> 2;
    const int wm   = w & 3;
    const int wn   = w >> 2;

    const int n0 = blockIdx.x * 64;
    const int o0 = blockIdx.y * 128;
    const int b  = blockIdx.z;
    const float* preb = g_pre + (size_t)b * CC * NS;

    float acc[2][4][4] = {};

    #pragma unroll 1
    for (int k0 = 0; k0 < CC; k0 += 32) {
        __syncthreads();
        if (tid < 128) {
            float wb[32];
            const float4* wr = (const float4*)(W + (size_t)(o0 + tid) * CC + k0);
            #pragma unroll
            for (int i = 0; i < 8; i++) *(float4*)&wb[4 * i] = wr[i];
            #pragma unroll
            for (int k = 0; k < 32; k++) Ws[k * 136 + tid] = tf32r(wb[k]);
        } else {
            const int j = (tid - 128) & 63;
            const int h = (tid - 128) >> 6;
            float xb[16];
            #pragma unroll
            for (int i = 0; i < 16; i++)
                xb[i] = tf32r(preb[(size_t)(k0 + 16 * h + i) * NS + n0 + j]);
            #pragma unroll
            for (int q = 0; q < 4; q++) {
                float4 f = make_float4(xb[0 + q], xb[4 + q], xb[8 + q], xb[12 + q]);
                *(float4*)&Xs[j * 36 + 8 * q + 4 * h] = f;
            }
        }
        __syncthreads();

        uint32_t aw[4][2][4];
        #pragma unroll
        for (int kc = 0; kc < 4; kc++)
            #pragma unroll
            for (int mt = 0; mt < 2; mt++) {
                int R = wm * 32 + mt * 16 + g;
                aw[kc][mt][0] = fb(Ws[(8 * kc + q4) * 136 + R]);
                aw[kc][mt][1] = fb(Ws[(8 * kc + q4) * 136 + R + 8]);
                aw[kc][mt][2] = fb(Ws[(8 * kc + q4 + 4) * 136 + R]);
                aw[kc][mt][3] = fb(Ws[(8 * kc + q4 + 4) * 136 + R + 8]);
            }

        #pragma unroll
        for (int nt = 0; nt < 4; nt++) {
            const float4 bq0 = *(const float4*)&Xs[(wn * 32 + nt * 8 + g) * 36 + 8 * q4];
            const float4 bq1 = *(const float4*)&Xs[(wn * 32 + nt * 8 + g) * 36 + 8 * q4 + 4];
            #pragma unroll
            for (int mt = 0; mt < 2; mt++) {
                mma_tf32(acc[mt][nt][0], acc[mt][nt][1], acc[mt][nt][2], acc[mt][nt][3],
                         aw[0][mt][0], aw[0][mt][1], aw[0][mt][2], aw[0][mt][3], fb(bq0.x), fb(bq0.y));
                mma_tf32(acc[mt][nt][0], acc[mt][nt][1], acc[mt][nt][2], acc[mt][nt][3],
                         aw[1][mt][0], aw[1][mt][1], aw[1][mt][2], aw[1][mt][3], fb(bq0.z), fb(bq0.w));
                mma_tf32(acc[mt][nt][0], acc[mt][nt][1], acc[mt][nt][2], acc[mt][nt][3],
                         aw[2][mt][0], aw[2][mt][1], aw[2][mt][2], aw[2][mt][3], fb(bq1.x), fb(bq1.y));
                mma_tf32(acc[mt][nt][0], acc[mt][nt][1], acc[mt][nt][2], acc[mt][nt][3],
                         aw[3][mt][0], aw[3][mt][1], aw[3][mt][2], aw[3][mt][3], fb(bq1.z), fb(bq1.w));
            }
        }
    }

    // ---- epilogue: add bias, write ----
    #pragma unroll
    for (int mt = 0; mt < 2; mt++) {
        const int r = o0 + wm * 32 + mt * 16 + g;
        const float bv0 = bias[r], bv1 = bias[r + 8];
        #pragma unroll
        for (int nt = 0; nt < 4; nt++) {
            size_t base = ((size_t)(b * CC) + r) * NS + n0 + wn * 32 + nt * 8 + 2 * q4;
            out[base]              = acc[mt][nt][0] + bv0;
            out[base + 1]          = acc[mt][nt][1] + bv0;
            out[base + 8 * NS]     = acc[mt][nt][2] + bv1;
            out[base + 8 * NS + 1] = acc[mt][nt][3] + bv1;
        }
    }
}

extern "C" void kernel_launch(void* const* d_in, const int* in_sizes, int n_in,
                              void* d_out, int out_size) {
    const float* qkv  = (const float*)d_in[0];
    const float* temp = (const float*)d_in[1];
    const float* W    = (const float*)d_in[2];
    const float* bias = (const float*)d_in[3];
    float* out = (float*)d_out;

    cudaFuncSetAttribute(attn_kernel, cudaFuncAttributeMaxDynamicSharedMemorySize, SM_BYTES);
    attn_kernel<<<dim3(NS / TQ, B_ * NH), 128, SM_BYTES>>>(qkv, temp);
    proj_kernel<<<dim3(NS / 64, CC / 128, B_), 256>>>(W, bias, out);
}

// round 15
// speedup vs baseline: 1.6938x; 1.6938x over previous
#include <cuda_runtime.h>
#include <cstdint>
#include <math.h>

// Problem constants
#define B_   4
#define NH   8
#define HD   32
#define NS   2304     // 48*48
#define CC   256
#define TQ   128      // q rows per CTA (4 warps x 32)
#define TK   64       // kv rows per tile
#define NT   (NS / TK) // 36

// dynamic smem layout (float offsets), K/V double-buffered; P never touches smem
#define QP_OFF  0                          // Q staging [32][136]
#define KT_OFF(bf)  (4352 + (bf) * 2304)   // K^ [64][36] k-interleaved (normalized)
#define VP_OFF(bf)  (8960 + (bf) * 2176)   // V~ [32][68] (c rows, chi-perm cols)
#define SM_FLOATS 13312
#define SM_BYTES  (SM_FLOATS * 4)          // 53248 B -> 3 CTAs/SM smem-wise

__device__ float g_pre[B_ * CC * NS];

__device__ __forceinline__ float tf32r(float x) {
    uint32_t u;
    asm("cvt.rna.tf32.f32 %0, %1;" : "=r"(u) : "f"(x));
    return __uint_as_float(u);
}
__device__ __forceinline__ uint32_t fb(float x) { return __float_as_uint(x); }
__device__ __forceinline__ float ex2f(float x) {
    float y;
    asm("ex2.approx.f32 %0, %1;" : "=f"(y) : "f"(x));
    return y;
}

__device__ __forceinline__ void mma_tf32(float& c0, float& c1, float& c2, float& c3,
                                         uint32_t a0, uint32_t a1, uint32_t a2, uint32_t a3,
                                         uint32_t b0, uint32_t b1) {
    asm volatile("mma.sync.aligned.m16n8k8.row.col.f32.tf32.tf32.f32 "
                 "{%0,%1,%2,%3}, {%4,%5,%6,%7}, {%8,%9}, {%0,%1,%2,%3};"
                 : "+f"(c0), "+f"(c1), "+f"(c2), "+f"(c3)
                 : "r"(a0), "r"(a1), "r"(a2), "r"(a3), "r"(b0), "r"(b1));
}

// ---------------------------------------------------------------------------
// Fused attention, tf32 mma.sync, double-buffered K/V.
// Norms folded into operands (Q^ = q*temp*log2e/||q||, K^ = k/||k||).
// P = 2^max(S,0) stays ENTIRELY in registers: the MMA2 k<->column mapping
// chi(kc, q4) = 8kc+2q4, chi(kc, q4+4) = 8kc+2q4+1 makes the S C-frag the
// exact A-frag; V smem uses the matching column permutation.
// ---------------------------------------------------------------------------
__global__ __launch_bounds__(128, 2) void attn_kernel(
    const float* __restrict__ qkv, const float* __restrict__ temp)
{
    extern __shared__ float sm[];

    const int tid  = threadIdx.x;
    const int lane = tid & 31;
    const int w    = tid >> 5;       // warp 0..3 -> q rows w*32..
    const int q4   = lane & 3;
    const int g    = lane >> 2;

    const int bh = blockIdx.y;
    const int b  = bh >> 3, hh = bh & 7;
    const int n0 = blockIdx.x * TQ;
    const float th = temp[hh] * 1.44269504089f;   // temp * log2e

    const size_t baseQ = ((size_t)(b * 3 * CC) + hh * HD) * NS;
    const size_t baseK = baseQ + (size_t)CC * NS;
    const size_t baseV = baseK + (size_t)CC * NS;

    // role split: threads 0-63 own K row j=tid; threads 64-127 own V row j=tid-64
    const int jK = tid;
    const int jV = tid - 64;
    // chi-permutation for V columns: pos = 16*((j>>1)&3) + 2*(j>>3) + (j&1)
    const int rjV = 16 * ((jV >> 1) & 3) + 2 * (jV >> 3) + (jV & 1);
    const bool isK = tid < 64;

    // ---- Q tile: thread owns q row n=tid; fold temp*log2e/||q|| into values ----
    {
        float qb[HD];
        float sq = 0.f;
        #pragma unroll
        for (int c = 0; c < HD; c++) {
            float v = qkv[baseQ + (size_t)c * NS + n0 + tid];
            sq += v * v;
            qb[c] = v;
        }
        const float qscale = th / fmaxf(sqrtf(sq), 1e-12f);
        #pragma unroll
        for (int c = 0; c < HD; c++)
            sm[QP_OFF + c * 136 + tid] = tf32r(qb[c] * qscale);
    }
    __syncthreads();

    // ---- persistent Q A-frags ----
    uint32_t aq[4][2][4];
    #pragma unroll
    for (int kc = 0; kc < 4; kc++)
        #pragma unroll
        for (int mt = 0; mt < 2; mt++) {
            int R = w * 32 + mt * 16 + g;
            aq[kc][mt][0] = fb(sm[QP_OFF + (8 * kc + q4) * 136 + R]);
            aq[kc][mt][1] = fb(sm[QP_OFF + (8 * kc + q4) * 136 + R + 8]);
            aq[kc][mt][2] = fb(sm[QP_OFF + (8 * kc + q4 + 4) * 136 + R]);
            aq[kc][mt][3] = fb(sm[QP_OFF + (8 * kc + q4 + 4) * 136 + R + 8]);
        }
    __syncthreads();   // QP staging dead

    // ---- direct gmem->convert->smem tile load; kbuf liveness is local ----
    #define LOAD_TILE(T, BF)                                                      \
    do {                                                                          \
        if (isK) {                                                                \
            float kbuf[HD];                                                       \
            float sk = 0.f;                                                       \
            _Pragma("unroll")                                                     \
            for (int c = 0; c < HD; c++) {                                        \
                float v = qkv[baseK + (size_t)c * NS + (T) * TK + jK];            \
                sk += v * v;                                                      \
                kbuf[c] = v;                                                      \
            }                                                                     \
            const float kscale = 1.0f / fmaxf(sqrtf(sk), 1e-12f);                 \
            _Pragma("unroll")                                                     \
            for (int c = 0; c < HD; c++) { kbuf[c] = tf32r(kbuf[c] * kscale); }   \
            _Pragma("unroll")                                                     \
            for (int q = 0; q < 4; q++)                                           \
                _Pragma("unroll")                                                 \
                for (int u = 0; u < 2; u++) {                                     \
                    float4 f = make_float4(kbuf[(4*u+0)*4+q], kbuf[(4*u+1)*4+q],  \
                                           kbuf[(4*u+2)*4+q], kbuf[(4*u+3)*4+q]); \
                    *(float4*)&sm[KT_OFF(BF) + jK * 36 + 8 * q + 4 * u] = f;      \
                }                                                                 \
        } else {                                                                  \
            _Pragma("unroll")                                                     \
            for (int c = 0; c < HD; c++)                                          \
                sm[VP_OFF(BF) + c * 68 + rjV] =                                   \
                    tf32r(qkv[baseV + (size_t)c * NS + (T) * TK + jV]);           \
        }                                                                         \
    } while (0)

    LOAD_TILE(0, 0);
    __syncthreads();

    float o[2][4][4] = {};
    float racc[2][2] = {};

    #pragma unroll 1
    for (int t = 0; t < NT; t++) {
        const int cur = t & 1, nxt = cur ^ 1;

        // ---- MMA1: S(32x64) = Q^(32x32) K^^T  (softmax arg directly) ----
        float s[2][8][4] = {};
        #pragma unroll
        for (int nt = 0; nt < 8; nt++) {
            const float4 bq0 = *(const float4*)&sm[KT_OFF(cur) + (nt * 8 + g) * 36 + 8 * q4];
            const float4 bq1 = *(const float4*)&sm[KT_OFF(cur) + (nt * 8 + g) * 36 + 8 * q4 + 4];
            #pragma unroll
            for (int mt = 0; mt < 2; mt++) {
                mma_tf32(s[mt][nt][0], s[mt][nt][1], s[mt][nt][2], s[mt][nt][3],
                         aq[0][mt][0], aq[0][mt][1], aq[0][mt][2], aq[0][mt][3], fb(bq0.x), fb(bq0.y));
                mma_tf32(s[mt][nt][0], s[mt][nt][1], s[mt][nt][2], s[mt][nt][3],
                         aq[1][mt][0], aq[1][mt][1], aq[1][mt][2], aq[1][mt][3], fb(bq0.z), fb(bq0.w));
                mma_tf32(s[mt][nt][0], s[mt][nt][1], s[mt][nt][2], s[mt][nt][3],
                         aq[2][mt][0], aq[2][mt][1], aq[2][mt][2], aq[2][mt][3], fb(bq1.x), fb(bq1.y));
                mma_tf32(s[mt][nt][0], s[mt][nt][1], s[mt][nt][2], s[mt][nt][3],
                         aq[3][mt][0], aq[3][mt][1], aq[3][mt][2], aq[3][mt][3], fb(bq1.z), fb(bq1.w));
            }
        }

        // ---- P = 2^max(S,0) in registers; C-frag IS the MMA2 A-frag ----
        // pa[mt][2nt+b] = P[row g][8nt+2q4+b], pb = row g+8 (chi mapping)
        float pa[2][16], pb[2][16];
        #pragma unroll
        for (int nt = 0; nt < 8; nt++)
            #pragma unroll
            for (int mt = 0; mt < 2; mt++) {
                float p00 = ex2f(fmaxf(s[mt][nt][0], 0.f));
                float p01 = ex2f(fmaxf(s[mt][nt][1], 0.f));
                float p10 = ex2f(fmaxf(s[mt][nt][2], 0.f));
                float p11 = ex2f(fmaxf(s[mt][nt][3], 0.f));
                racc[mt][0] += p00 + p01;
                racc[mt][1] += p10 + p11;
                pa[mt][2 * nt]     = p00;
                pa[mt][2 * nt + 1] = p01;
                pb[mt][2 * nt]     = p10;
                pb[mt][2 * nt + 1] = p11;
            }

        // ---- MMA2: O(32x32) += P(32x64) V(64x32), chi-permuted V ----
        #pragma unroll
        for (int nt2 = 0; nt2 < 4; nt2++) {
            float bv[16];
            const int vr = VP_OFF(cur) + (nt2 * 8 + g) * 68 + 16 * q4;
            #pragma unroll
            for (int u = 0; u < 4; u++)
                *(float4*)&bv[4 * u] = *(const float4*)&sm[vr + 4 * u];
            #pragma unroll
            for (int mt = 0; mt < 2; mt++)
                #pragma unroll
                for (int kc = 0; kc < 8; kc++)
                    mma_tf32(o[mt][nt2][0], o[mt][nt2][1], o[mt][nt2][2], o[mt][nt2][3],
                             fb(pa[mt][2 * kc]), fb(pb[mt][2 * kc]),
                             fb(pa[mt][2 * kc + 1]), fb(pb[mt][2 * kc + 1]),
                             fb(bv[2 * kc]), fb(bv[2 * kc + 1]));
        }

        // ---- load tile t+1 into buffer nxt ----
        if (t + 1 < NT) LOAD_TILE(t + 1, nxt);
        __syncthreads();
    }
    #undef LOAD_TILE

    // ---- rowsum reduce across the 4-lane q4 group ----
    #pragma unroll
    for (int mt = 0; mt < 2; mt++)
        #pragma unroll
        for (int hf = 0; hf < 2; hf++) {
            float v = racc[mt][hf];
            v += __shfl_xor_sync(0xffffffffu, v, 1);
            v += __shfl_xor_sync(0xffffffffu, v, 2);
            racc[mt][hf] = 1.0f / v;
        }

    // ---- write O to g_pre[b, hh*HD + c, n] ----
    const size_t baseO = ((size_t)(b * CC) + hh * HD) * NS;
    #pragma unroll
    for (int mt = 0; mt < 2; mt++) {
        const int row = n0 + w * 32 + mt * 16 + g;
        #pragma unroll
        for (int nt2 = 0; nt2 < 4; nt2++) {
            int c0 = nt2 * 8 + 2 * q4;
            g_pre[baseO + (size_t)c0 * NS + row]           = o[mt][nt2][0] * racc[mt][0];
            g_pre[baseO + (size_t)(c0 + 1) * NS + row]     = o[mt][nt2][1] * racc[mt][0];
            g_pre[baseO + (size_t)c0 * NS + row + 8]       = o[mt][nt2][2] * racc[mt][1];
            g_pre[baseO + (size_t)(c0 + 1) * NS + row + 8] = o[mt][nt2][3] * racc[mt][1];
        }
    }
}

// ---------------------------------------------------------------------------
// 1x1 conv as tf32 warp-MMA GEMM (round-8 version: 24.9us measured)
// ---------------------------------------------------------------------------
__global__ __launch_bounds__(256, 2) void proj_kernel(
    const float* __restrict__ W, const float* __restrict__ bias,
    float* __restrict__ out)
{
    __shared__ float Ws[32 * 136];   // [k][o], pitch 136
    __shared__ float Xs[64 * 36];    // [n][k-interleaved], pitch 36

    const int tid  = threadIdx.x;
    const int lane = tid & 31;
    const int w    = tid >> 5;
    const int q4   = lane & 3;
    const int g    = lane >> 2;
    const int wm   = w & 3;
    const int wn   = w >> 2;

    const int n0 = blockIdx.x * 64;
    const int o0 = blockIdx.y * 128;
    const int b  = blockIdx.z;
    const float* preb = g_pre + (size_t)b * CC * NS;

    float acc[2][4][4] = {};

    #pragma unroll 1
    for (int k0 = 0; k0 < CC; k0 += 32) {
        __syncthreads();
        if (tid < 128) {
            float wb[32];
            const float4* wr = (const float4*)(W + (size_t)(o0 + tid) * CC + k0);
            #pragma unroll
            for (int i = 0; i < 8; i++) *(float4*)&wb[4 * i] = wr[i];
            #pragma unroll
            for (int k = 0; k < 32; k++) Ws[k * 136 + tid] = tf32r(wb[k]);
        } else {
            const int j = (tid - 128) & 63;
            const int h = (tid - 128) >> 6;
            float xb[16];
            #pragma unroll
            for (int i = 0; i < 16; i++)
                xb[i] = tf32r(preb[(size_t)(k0 + 16 * h + i) * NS + n0 + j]);
            #pragma unroll
            for (int q = 0; q < 4; q++) {
                float4 f = make_float4(xb[0 + q], xb[4 + q], xb[8 + q], xb[12 + q]);
                *(float4*)&Xs[j * 36 + 8 * q + 4 * h] = f;
            }
        }
        __syncthreads();

        uint32_t aw[4][2][4];
        #pragma unroll
        for (int kc = 0; kc < 4; kc++)
            #pragma unroll
            for (int mt = 0; mt < 2; mt++) {
                int R = wm * 32 + mt * 16 + g;
                aw[kc][mt][0] = fb(Ws[(8 * kc + q4) * 136 + R]);
                aw[kc][mt][1] = fb(Ws[(8 * kc + q4) * 136 + R + 8]);
                aw[kc][mt][2] = fb(Ws[(8 * kc + q4 + 4) * 136 + R]);
                aw[kc][mt][3] = fb(Ws[(8 * kc + q4 + 4) * 136 + R + 8]);
            }

        #pragma unroll
        for (int nt = 0; nt < 4; nt++) {
            const float4 bq0 = *(const float4*)&Xs[(wn * 32 + nt * 8 + g) * 36 + 8 * q4];
            const float4 bq1 = *(const float4*)&Xs[(wn * 32 + nt * 8 + g) * 36 + 8 * q4 + 4];
            #pragma unroll
            for (int mt = 0; mt < 2; mt++) {
                mma_tf32(acc[mt][nt][0], acc[mt][nt][1], acc[mt][nt][2], acc[mt][nt][3],
                         aw[0][mt][0], aw[0][mt][1], aw[0][mt][2], aw[0][mt][3], fb(bq0.x), fb(bq0.y));
                mma_tf32(acc[mt][nt][0], acc[mt][nt][1], acc[mt][nt][2], acc[mt][nt][3],
                         aw[1][mt][0], aw[1][mt][1], aw[1][mt][2], aw[1][mt][3], fb(bq0.z), fb(bq0.w));
                mma_tf32(acc[mt][nt][0], acc[mt][nt][1], acc[mt][nt][2], acc[mt][nt][3],
                         aw[2][mt][0], aw[2][mt][1], aw[2][mt][2], aw[2][mt][3], fb(bq1.x), fb(bq1.y));
                mma_tf32(acc[mt][nt][0], acc[mt][nt][1], acc[mt][nt][2], acc[mt][nt][3],
                         aw[3][mt][0], aw[3][mt][1], aw[3][mt][2], aw[3][mt][3], fb(bq1.z), fb(bq1.w));
            }
        }
    }

    // ---- epilogue: add bias, write ----
    #pragma unroll
    for (int mt = 0; mt < 2; mt++) {
        const int r = o0 + wm * 32 + mt * 16 + g;
        const float bv0 = bias[r], bv1 = bias[r + 8];
        #pragma unroll
        for (int nt = 0; nt < 4; nt++) {
            size_t base = ((size_t)(b * CC) + r) * NS + n0 + wn * 32 + nt * 8 + 2 * q4;
            out[base]              = acc[mt][nt][0] + bv0;
            out[base + 1]          = acc[mt][nt][1] + bv0;
            out[base + 8 * NS]     = acc[mt][nt][2] + bv1;
            out[base + 8 * NS + 1] = acc[mt][nt][3] + bv1;
        }
    }
}

extern "C" void kernel_launch(void* const* d_in, const int* in_sizes, int n_in,
                              void* d_out, int out_size) {
    const float* qkv  = (const float*)d_in[0];
    const float* temp = (const float*)d_in[1];
    const float* W    = (const float*)d_in[2];
    const float* bias = (const float*)d_in[3];
    float* out = (float*)d_out;

    cudaFuncSetAttribute(attn_kernel, cudaFuncAttributeMaxDynamicSharedMemorySize, SM_BYTES);
    attn_kernel<<<dim3(NS / TQ, B_ * NH), 128, SM_BYTES>>>(qkv, temp);
    proj_kernel<<<dim3(NS / 64, CC / 128, B_), 256>>>(W, bias, out);
}

// round 16
// speedup vs baseline: 1.7605x; 1.0394x over previous
#include <cuda_runtime.h>
#include <cstdint>
#include <math.h>

// Problem constants
#define B_   4
#define NH   8
#define HD   32
#define NS   2304     // 48*48
#define CC   256
#define TQ   128      // q rows per CTA (4 warps x 32)
#define TK   64       // kv rows per tile
#define NT   (NS / TK) // 36

// dynamic smem layout (float offsets), K/V double-buffered; P never touches smem
#define QP_OFF  0                          // Q staging [32][136]
#define KT_OFF(bf)  (4352 + (bf) * 2304)   // K^ [64][36] k-interleaved (normalized)
#define VP_OFF(bf)  (8960 + (bf) * 2176)   // V~ [32][68] (c rows, chi-perm cols)
#define SM_FLOATS 13312
#define SM_BYTES  (SM_FLOATS * 4)          // 53248 B

__device__ float g_pre[B_ * CC * NS];

__device__ __forceinline__ float tf32r(float x) {
    uint32_t u;
    asm("cvt.rna.tf32.f32 %0, %1;" : "=r"(u) : "f"(x));
    return __uint_as_float(u);
}
__device__ __forceinline__ uint32_t fb(float x) { return __float_as_uint(x); }
__device__ __forceinline__ float ex2f(float x) {
    float y;
    asm("ex2.approx.f32 %0, %1;" : "=f"(y) : "f"(x));
    return y;
}

__device__ __forceinline__ void mma_tf32(float& c0, float& c1, float& c2, float& c3,
                                         uint32_t a0, uint32_t a1, uint32_t a2, uint32_t a3,
                                         uint32_t b0, uint32_t b1) {
    asm volatile("mma.sync.aligned.m16n8k8.row.col.f32.tf32.tf32.f32 "
                 "{%0,%1,%2,%3}, {%4,%5,%6,%7}, {%8,%9}, {%0,%1,%2,%3};"
                 : "+f"(c0), "+f"(c1), "+f"(c2), "+f"(c3)
                 : "r"(a0), "r"(a1), "r"(a2), "r"(a3), "r"(b0), "r"(b1));
}

// ---------------------------------------------------------------------------
// Fused attention, tf32 mma.sync, double-buffered K/V, chi-mapped MMA2 (P in
// registers). K/V for tile t+1 prefetched into regs AFTER softmax (short
// liveness: covered by MMA2), stored to smem at tile end.
// ---------------------------------------------------------------------------
__global__ __launch_bounds__(128, 2) void attn_kernel(
    const float* __restrict__ qkv, const float* __restrict__ temp)
{
    extern __shared__ float sm[];

    const int tid  = threadIdx.x;
    const int lane = tid & 31;
    const int w    = tid >> 5;       // warp 0..3 -> q rows w*32..
    const int q4   = lane & 3;
    const int g    = lane >> 2;

    const int bh = blockIdx.y;
    const int b  = bh >> 3, hh = bh & 7;
    const int n0 = blockIdx.x * TQ;
    const float th = temp[hh] * 1.44269504089f;   // temp * log2e

    const size_t baseQ = ((size_t)(b * 3 * CC) + hh * HD) * NS;
    const size_t baseK = baseQ + (size_t)CC * NS;
    const size_t baseV = baseK + (size_t)CC * NS;

    // role split: threads 0-63 own K row j=tid; threads 64-127 own V row j=tid-64
    const int jK = tid;
    const int jV = tid - 64;
    // chi-permutation for V columns: pos = 16*((j>>1)&3) + 2*(j>>3) + (j&1)
    const int rjV = 16 * ((jV >> 1) & 3) + 2 * (jV >> 3) + (jV & 1);
    const bool isK = tid < 64;
    const size_t ldbase = isK ? (baseK + jK) : (baseV + jV);

    // ---- Q tile: thread owns q row n=tid; fold temp*log2e/||q|| into values ----
    {
        float qb[HD];
        float sq = 0.f;
        #pragma unroll
        for (int c = 0; c < HD; c++) {
            float v = qkv[baseQ + (size_t)c * NS + n0 + tid];
            sq += v * v;
            qb[c] = v;
        }
        const float qscale = th / fmaxf(sqrtf(sq), 1e-12f);
        #pragma unroll
        for (int c = 0; c < HD; c++)
            sm[QP_OFF + c * 136 + tid] = tf32r(qb[c] * qscale);
    }
    __syncthreads();

    // ---- persistent Q A-frags ----
    uint32_t aq[4][2][4];
    #pragma unroll
    for (int kc = 0; kc < 4; kc++)
        #pragma unroll
        for (int mt = 0; mt < 2; mt++) {
            int R = w * 32 + mt * 16 + g;
            aq[kc][mt][0] = fb(sm[QP_OFF + (8 * kc + q4) * 136 + R]);
            aq[kc][mt][1] = fb(sm[QP_OFF + (8 * kc + q4) * 136 + R + 8]);
            aq[kc][mt][2] = fb(sm[QP_OFF + (8 * kc + q4 + 4) * 136 + R]);
            aq[kc][mt][3] = fb(sm[QP_OFF + (8 * kc + q4 + 4) * 136 + R + 8]);
        }
    __syncthreads();   // QP staging dead

    // ---- convert+store kb -> smem buffer (K normalized+interleaved; V chi) ----
    float kb[HD];
    #define STORE_TILE(BF)                                                        \
    do {                                                                          \
        if (isK) {                                                                \
            float sk = 0.f;                                                       \
            _Pragma("unroll")                                                     \
            for (int c = 0; c < HD; c++) { sk += kb[c] * kb[c]; }                 \
            const float kscale = 1.0f / fmaxf(sqrtf(sk), 1e-12f);                 \
            _Pragma("unroll")                                                     \
            for (int c = 0; c < HD; c++) { kb[c] = tf32r(kb[c] * kscale); }       \
            _Pragma("unroll")                                                     \
            for (int q = 0; q < 4; q++)                                           \
                _Pragma("unroll")                                                 \
                for (int u = 0; u < 2; u++) {                                     \
                    float4 f = make_float4(kb[(4*u+0)*4+q], kb[(4*u+1)*4+q],      \
                                           kb[(4*u+2)*4+q], kb[(4*u+3)*4+q]);     \
                    *(float4*)&sm[KT_OFF(BF) + jK * 36 + 8 * q + 4 * u] = f;      \
                }                                                                 \
        } else {                                                                  \
            _Pragma("unroll")                                                     \
            for (int c = 0; c < HD; c++)                                          \
                sm[VP_OFF(BF) + c * 68 + rjV] = tf32r(kb[c]);                     \
        }                                                                         \
    } while (0)

    // prologue: tile 0
    #pragma unroll
    for (int c = 0; c < HD; c++) kb[c] = qkv[ldbase + (size_t)c * NS];
    STORE_TILE(0);
    __syncthreads();

    float o[2][4][4] = {};
    float racc[2][2] = {};

    #pragma unroll 1
    for (int t = 0; t < NT; t++) {
        const int cur = t & 1, nxt = cur ^ 1;

        // ---- MMA1: S(32x64) = Q^(32x32) K^^T  (softmax arg directly) ----
        float s[2][8][4] = {};
        #pragma unroll
        for (int nt = 0; nt < 8; nt++) {
            const float4 bq0 = *(const float4*)&sm[KT_OFF(cur) + (nt * 8 + g) * 36 + 8 * q4];
            const float4 bq1 = *(const float4*)&sm[KT_OFF(cur) + (nt * 8 + g) * 36 + 8 * q4 + 4];
            #pragma unroll
            for (int mt = 0; mt < 2; mt++) {
                mma_tf32(s[mt][nt][0], s[mt][nt][1], s[mt][nt][2], s[mt][nt][3],
                         aq[0][mt][0], aq[0][mt][1], aq[0][mt][2], aq[0][mt][3], fb(bq0.x), fb(bq0.y));
                mma_tf32(s[mt][nt][0], s[mt][nt][1], s[mt][nt][2], s[mt][nt][3],
                         aq[1][mt][0], aq[1][mt][1], aq[1][mt][2], aq[1][mt][3], fb(bq0.z), fb(bq0.w));
                mma_tf32(s[mt][nt][0], s[mt][nt][1], s[mt][nt][2], s[mt][nt][3],
                         aq[2][mt][0], aq[2][mt][1], aq[2][mt][2], aq[2][mt][3], fb(bq1.x), fb(bq1.y));
                mma_tf32(s[mt][nt][0], s[mt][nt][1], s[mt][nt][2], s[mt][nt][3],
                         aq[3][mt][0], aq[3][mt][1], aq[3][mt][2], aq[3][mt][3], fb(bq1.z), fb(bq1.w));
            }
        }

        // ---- P = 2^max(S,0) in registers; C-frag IS the MMA2 A-frag ----
        float pa[2][16], pb[2][16];
        #pragma unroll
        for (int nt = 0; nt < 8; nt++)
            #pragma unroll
            for (int mt = 0; mt < 2; mt++) {
                float p00 = ex2f(fmaxf(s[mt][nt][0], 0.f));
                float p01 = ex2f(fmaxf(s[mt][nt][1], 0.f));
                float p10 = ex2f(fmaxf(s[mt][nt][2], 0.f));
                float p11 = ex2f(fmaxf(s[mt][nt][3], 0.f));
                racc[mt][0] += p00 + p01;
                racc[mt][1] += p10 + p11;
                pa[mt][2 * nt]     = p00;
                pa[mt][2 * nt + 1] = p01;
                pb[mt][2 * nt]     = p10;
                pb[mt][2 * nt + 1] = p11;
            }

        // ---- prefetch tile t+1 into regs (s[] dead; covered by MMA2 below) ----
        if (t + 1 < NT) {
            const size_t base1 = ldbase + (size_t)(t + 1) * TK;
            #pragma unroll
            for (int c = 0; c < HD; c++) kb[c] = qkv[base1 + (size_t)c * NS];
        }

        // ---- MMA2: O(32x32) += P(32x64) V(64x32), chi-permuted V ----
        #pragma unroll
        for (int nt2 = 0; nt2 < 4; nt2++) {
            float bv[16];
            const int vr = VP_OFF(cur) + (nt2 * 8 + g) * 68 + 16 * q4;
            #pragma unroll
            for (int u = 0; u < 4; u++)
                *(float4*)&bv[4 * u] = *(const float4*)&sm[vr + 4 * u];
            #pragma unroll
            for (int mt = 0; mt < 2; mt++)
                #pragma unroll
                for (int kc = 0; kc < 8; kc++)
                    mma_tf32(o[mt][nt2][0], o[mt][nt2][1], o[mt][nt2][2], o[mt][nt2][3],
                             fb(pa[mt][2 * kc]), fb(pb[mt][2 * kc]),
                             fb(pa[mt][2 * kc + 1]), fb(pb[mt][2 * kc + 1]),
                             fb(bv[2 * kc]), fb(bv[2 * kc + 1]));
        }

        // ---- convert+store tile t+1 into buffer nxt ----
        if (t + 1 < NT) STORE_TILE(nxt);
        __syncthreads();
    }
    #undef STORE_TILE

    // ---- rowsum reduce across the 4-lane q4 group ----
    #pragma unroll
    for (int mt = 0; mt < 2; mt++)
        #pragma unroll
        for (int hf = 0; hf < 2; hf++) {
            float v = racc[mt][hf];
            v += __shfl_xor_sync(0xffffffffu, v, 1);
            v += __shfl_xor_sync(0xffffffffu, v, 2);
            racc[mt][hf] = 1.0f / v;
        }

    // ---- write O to g_pre[b, hh*HD + c, n] ----
    const size_t baseO = ((size_t)(b * CC) + hh * HD) * NS;
    #pragma unroll
    for (int mt = 0; mt < 2; mt++) {
        const int row = n0 + w * 32 + mt * 16 + g;
        #pragma unroll
        for (int nt2 = 0; nt2 < 4; nt2++) {
            int c0 = nt2 * 8 + 2 * q4;
            g_pre[baseO + (size_t)c0 * NS + row]           = o[mt][nt2][0] * racc[mt][0];
            g_pre[baseO + (size_t)(c0 + 1) * NS + row]     = o[mt][nt2][1] * racc[mt][0];
            g_pre[baseO + (size_t)c0 * NS + row + 8]       = o[mt][nt2][2] * racc[mt][1];
            g_pre[baseO + (size_t)(c0 + 1) * NS + row + 8] = o[mt][nt2][3] * racc[mt][1];
        }
    }
}

// ---------------------------------------------------------------------------
// 1x1 conv as tf32 warp-MMA GEMM (round-8 version, unchanged)
// ---------------------------------------------------------------------------
__global__ __launch_bounds__(256, 2) void proj_kernel(
    const float* __restrict__ W, const float* __restrict__ bias,
    float* __restrict__ out)
{
    __shared__ float Ws[32 * 136];   // [k][o], pitch 136
    __shared__ float Xs[64 * 36];    // [n][k-interleaved], pitch 36

    const int tid  = threadIdx.x;
    const int lane = tid & 31;
    const int w    = tid >> 5;
    const int q4   = lane & 3;
    const int g    = lane >> 2;
    const int wm   = w & 3;
    const int wn   = w >> 2;

    const int n0 = blockIdx.x * 64;
    const int o0 = blockIdx.y * 128;
    const int b  = blockIdx.z;
    const float* preb = g_pre + (size_t)b * CC * NS;

    float acc[2][4][4] = {};

    #pragma unroll 1
    for (int k0 = 0; k0 < CC; k0 += 32) {
        __syncthreads();
        if (tid < 128) {
            float wb[32];
            const float4* wr = (const float4*)(W + (size_t)(o0 + tid) * CC + k0);
            #pragma unroll
            for (int i = 0; i < 8; i++) *(float4*)&wb[4 * i] = wr[i];
            #pragma unroll
            for (int k = 0; k < 32; k++) Ws[k * 136 + tid] = tf32r(wb[k]);
        } else {
            const int j = (tid - 128) & 63;
            const int h = (tid - 128) >> 6;
            float xb[16];
            #pragma unroll
            for (int i = 0; i < 16; i++)
                xb[i] = tf32r(preb[(size_t)(k0 + 16 * h + i) * NS + n0 + j]);
            #pragma unroll
            for (int q = 0; q < 4; q++) {
                float4 f = make_float4(xb[0 + q], xb[4 + q], xb[8 + q], xb[12 + q]);
                *(float4*)&Xs[j * 36 + 8 * q + 4 * h] = f;
            }
        }
        __syncthreads();

        uint32_t aw[4][2][4];
        #pragma unroll
        for (int kc = 0; kc < 4; kc++)
            #pragma unroll
            for (int mt = 0; mt < 2; mt++) {
                int R = wm * 32 + mt * 16 + g;
                aw[kc][mt][0] = fb(Ws[(8 * kc + q4) * 136 + R]);
                aw[kc][mt][1] = fb(Ws[(8 * kc + q4) * 136 + R + 8]);
                aw[kc][mt][2] = fb(Ws[(8 * kc + q4 + 4) * 136 + R]);
                aw[kc][mt][3] = fb(Ws[(8 * kc + q4 + 4) * 136 + R + 8]);
            }

        #pragma unroll
        for (int nt = 0; nt < 4; nt++) {
            const float4 bq0 = *(const float4*)&Xs[(wn * 32 + nt * 8 + g) * 36 + 8 * q4];
            const float4 bq1 = *(const float4*)&Xs[(wn * 32 + nt * 8 + g) * 36 + 8 * q4 + 4];
            #pragma unroll
            for (int mt = 0; mt < 2; mt++) {
                mma_tf32(acc[mt][nt][0], acc[mt][nt][1], acc[mt][nt][2], acc[mt][nt][3],
                         aw[0][mt][0], aw[0][mt][1], aw[0][mt][2], aw[0][mt][3], fb(bq0.x), fb(bq0.y));
                mma_tf32(acc[mt][nt][0], acc[mt][nt][1], acc[mt][nt][2], acc[mt][nt][3],
                         aw[1][mt][0], aw[1][mt][1], aw[1][mt][2], aw[1][mt][3], fb(bq0.z), fb(bq0.w));
                mma_tf32(acc[mt][nt][0], acc[mt][nt][1], acc[mt][nt][2], acc[mt][nt][3],
                         aw[2][mt][0], aw[2][mt][1], aw[2][mt][2], aw[2][mt][3], fb(bq1.x), fb(bq1.y));
                mma_tf32(acc[mt][nt][0], acc[mt][nt][1], acc[mt][nt][2], acc[mt][nt][3],
                         aw[3][mt][0], aw[3][mt][1], aw[3][mt][2], aw[3][mt][3], fb(bq1.z), fb(bq1.w));
            }
        }
    }

    // ---- epilogue: add bias, write ----
    #pragma unroll
    for (int mt = 0; mt < 2; mt++) {
        const int r = o0 + wm * 32 + mt * 16 + g;
        const float bv0 = bias[r], bv1 = bias[r + 8];
        #pragma unroll
        for (int nt = 0; nt < 4; nt++) {
            size_t base = ((size_t)(b * CC) + r) * NS + n0 + wn * 32 + nt * 8 + 2 * q4;
            out[base]              = acc[mt][nt][0] + bv0;
            out[base + 1]          = acc[mt][nt][1] + bv0;
            out[base + 8 * NS]     = acc[mt][nt][2] + bv1;
            out[base + 8 * NS + 1] = acc[mt][nt][3] + bv1;
        }
    }
}

extern "C" void kernel_launch(void* const* d_in, const int* in_sizes, int n_in,
                              void* d_out, int out_size) {
    const float* qkv  = (const float*)d_in[0];
    const float* temp = (const float*)d_in[1];
    const float* W    = (const float*)d_in[2];
    const float* bias = (const float*)d_in[3];
    float* out = (float*)d_out;

    cudaFuncSetAttribute(attn_kernel, cudaFuncAttributeMaxDynamicSharedMemorySize, SM_BYTES);
    attn_kernel<<<dim3(NS / TQ, B_ * NH), 128, SM_BYTES>>>(qkv, temp);
    proj_kernel<<<dim3(NS / 64, CC / 128, B_), 256>>>(W, bias, out);
}